// round 15
// baseline (speedup 1.0000x reference)
#include <cuda_runtime.h>
#include <math.h>

#define DIMX   20
#define DD     21
#define NPT    2048
#define MCc    32
#define UNITS  128
#define TP     16
#define BTOT   69632
#define NTILES (BTOT / TP)
#define THREADS 512
#define NCTA   148

#define SIGc   0.2f
#define MUc    0.05f
#define Rc     0.05f
#define DELTAc 0.01f

__device__ float g_WT[4 * UNITS * UNITS];      // [mat][a][b] = W[b][a]
__device__ float g_UcatT[5 * UNITS * 24];      // [v][j][24] padded
__device__ float g_X[BTOT * DD];
__device__ float g_FP[BTOT * DD];
__device__ float g_FVAL[BTOT];
__device__ unsigned g_bar = 0;                 // monotonic grid barrier

// smem layout (floats)
#define SM_X    0                        // 336
#define SM_S    336                      // 3 * 2048  [k][p]
#define SM_Z    (SM_S + 3 * 2048)
#define SM_G    (SM_Z + 3 * 2048)
#define SM_R    (SM_G + 3 * 2048)
#define SM_H    (SM_R + 3 * 2048)
#define SM_SR   (SM_H + 3 * 2048)        // scratch: chol L / s*r / da1
#define SM_FRED (SM_SR + 2048)           // 64
#define SM_XU   (SM_FRED + 64)           // 4 * 2048, layout [p][j]
#define SM_TOT  (SM_XU + 4 * 2048)       // 41360 floats = 165440 B

typedef unsigned long long u64t;

__device__ __forceinline__ u64t pack2(float lo, float hi) {
    u64t r;
    asm("mov.b64 %0, {%1, %2};" : "=l"(r) : "f"(lo), "f"(hi));
    return r;
}
__device__ __forceinline__ float2 unpack2(u64t v) {
    float2 f;
    asm("mov.b64 {%0, %1}, %2;" : "=f"(f.x), "=f"(f.y) : "l"(v));
    return f;
}
__device__ __forceinline__ u64t ffma2(u64t a, u64t b, u64t c) {
    u64t d;
    asm("fma.rn.f32x2 %0, %1, %2, %3;" : "=l"(d) : "l"(a), "l"(b), "l"(c));
    return d;
}
__device__ __forceinline__ float ftanh(float x) {
    float ax = fabsf(x);
    float t = __expf(-2.0f * ax);
    float r = __fdividef(1.0f - t, 1.0f + t);
    return copysignf(r, x);
}

// grid barrier: monotonic counter, safe across graph replays
__device__ __forceinline__ void grid_barrier() {
    __syncthreads();
    if (threadIdx.x == 0) {
        __threadfence();
        unsigned old = atomicAdd(&g_bar, 1u);
        unsigned target = (old / NCTA + 1u) * NCTA;
        while (*(volatile unsigned*)&g_bar < target) { }
        __threadfence();
    }
    __syncthreads();
}

__device__ __forceinline__ void st4(float* dst, const float a[4], int j, int p0) {
    *(float4*)&dst[j * TP + p0] = make_float4(a[0], a[1], a[2], a[3]);
}
__device__ __forceinline__ void mm1(u64t& a0, u64t& a1, const float* __restrict__ W,
                                    const float* S, int j, int p0) {
    #pragma unroll 8
    for (int k = 0; k < UNITS; k++) {
        float wv = W[k * UNITS + j];
        u64t wp = pack2(wv, wv);
        ulonglong2 s = *(const ulonglong2*)&S[k * TP + p0];
        a0 = ffma2(s.x, wp, a0);
        a1 = ffma2(s.y, wp, a1);
    }
}
__device__ __forceinline__ void mmX(float acc[4], const float* __restrict__ U,
                                    const float* X, int j, int p0) {
    #pragma unroll
    for (int d = 0; d < DD; d++) {
        float wv = U[d * UNITS + j];
        float4 s = *(const float4*)&X[d * TP + p0];
        acc[0] += s.x * wv; acc[1] += s.y * wv; acc[2] += s.z * wv; acc[3] += s.w * wv;
    }
}
__device__ __forceinline__ void tanh4(float out[4], u64t a0, u64t a1) {
    float2 t0 = unpack2(a0), t1 = unpack2(a1);
    out[0] = ftanh(t0.x); out[1] = ftanh(t0.y); out[2] = ftanh(t1.x); out[3] = ftanh(t1.y);
}
// rebuild f32x2 accumulator init from smem XU ([p][j] layout)
__device__ __forceinline__ void ldxu(u64t& a0, u64t& a1, const float* XU, int j, int p0) {
    float v0 = XU[(p0 + 0) * UNITS + j];
    float v1 = XU[(p0 + 1) * UNITS + j];
    float v2 = XU[(p0 + 2) * UNITS + j];
    float v3 = XU[(p0 + 3) * UNITS + j];
    a0 = pack2(v0, v1); a1 = pack2(v2, v3);
}

__global__ __launch_bounds__(THREADS, 1)
void dgm_persistent(const float* __restrict__ inputs, const float* __restrict__ eps,
                    const float* __restrict__ w1, const float* __restrict__ b1,
                    const float* __restrict__ uz, const float* __restrict__ wz, const float* __restrict__ bz,
                    const float* __restrict__ ug, const float* __restrict__ wg, const float* __restrict__ bg,
                    const float* __restrict__ ur, const float* __restrict__ wr, const float* __restrict__ br,
                    const float* __restrict__ uh, const float* __restrict__ wh, const float* __restrict__ bh,
                    const float* __restrict__ wout, const float* __restrict__ bout,
                    float* __restrict__ out)
{
    extern __shared__ float sm[];
    const int tid = threadIdx.x;
    const int cta = blockIdx.x;
    const int gthread = cta * THREADS + tid;
    const int gstride = NCTA * THREADS;

    // ================= phase 0: prep + build =================
    for (int t = gthread; t < 4 * UNITS * UNITS; t += gstride) {
        int mat = t >> 14;
        int r   = t & 16383;
        int a   = r >> 7;
        int b   = r & 127;
        const float* W = (mat == 0) ? wz : (mat == 1) ? wg : (mat == 2) ? wr : wh;
        g_WT[t] = W[b * UNITS + a];
    }
    for (int t = gthread; t < 5 * UNITS * 24; t += gstride) {
        int v = t / (UNITS * 24);
        int r = t % (UNITS * 24);
        int jj = r / 24;
        int d = r % 24;
        const float* U = (v == 0) ? uz : (v == 1) ? ug : (v == 2) ? ur : (v == 3) ? uh : w1;
        g_UcatT[t] = (d < DD) ? U[d * UNITS + jj] : 0.0f;
    }

    if (tid == 0) {
        double Ld[DIMX][DIMX];
        for (int i = 0; i < DIMX; i++) {
            for (int j2 = 0; j2 <= i; j2++) {
                double s = 0.01 * (0.5 + (i == j2 ? 0.5 : 0.0));
                for (int k = 0; k < j2; k++) s -= Ld[i][k] * Ld[j2][k];
                Ld[i][j2] = (i == j2) ? sqrt(s) : s / Ld[j2][j2];
            }
        }
        for (int i = 0; i < DIMX; i++)
            for (int j2 = 0; j2 < DIMX; j2++)
                sm[SM_SR + i * DIMX + j2] = (j2 <= i) ? (float)Ld[i][j2] : 0.0f;
    }
    __syncthreads();
    const float* Lsm = &sm[SM_SR];

    for (int r = gthread; r < BTOT; r += gstride) {
        if (r < 4096) {
            #pragma unroll
            for (int d = 0; d < DD; d++) g_X[r * DD + d] = inputs[r * DD + d];
        } else {
            int q = r - 4096;
            int m = q >> 11;
            int n = q & 2047;
            float xr[DD];
            #pragma unroll
            for (int d = 0; d < DD; d++) xr[d] = inputs[n * DD + d];
            float e[DIMX];
            #pragma unroll
            for (int d = 0; d < DIMX; d++) e[d] = eps[(m * NPT + n) * DIMX + d];
            #pragma unroll
            for (int k = 0; k < DIMX; k++) {
                float acc = 0.f;
                #pragma unroll
                for (int d = 0; d < DIMX; d++) acc += e[d] * Lsm[k * DIMX + d];
                float sample = xr[k] + acc;
                float viol = sample * (SIGc * xr[k]);
                g_X[r * DD + k] = xr[k] + viol;
            }
            g_X[r * DD + DIMX] = xr[DIMX];
        }
    }

    grid_barrier();

    // ================= phase 1: main tile loop =================
    const int j  = tid & 127;
    const int pg = tid >> 7;
    const int p0 = pg * 4;

    for (int tile = cta; tile < NTILES; tile += NCTA) {
        const int base = tile * TP;
        const bool doGrad = !(tile >= 128 && tile < 256);

        __syncthreads();   // protect smem reuse across tiles
        for (int t = tid; t < TP * DD; t += THREADS) {
            int p = t / DD, d = t % DD;
            sm[SM_X + d * TP + p] = g_X[(base + p) * DD + d];
        }
        __syncthreads();

        // ---- prologue: x@U + b -> smem XU ([p][j]); s0 ----
        float s_cur[4];
        {
            float acc[4];
            float bb;
            bb = bz[j];
            acc[0]=acc[1]=acc[2]=acc[3]=bb; mmX(acc, uz, &sm[SM_X], j, p0);
            #pragma unroll
            for (int i = 0; i < 4; i++) sm[SM_XU + 0 * 2048 + (p0 + i) * UNITS + j] = acc[i];
            bb = bg[j];
            acc[0]=acc[1]=acc[2]=acc[3]=bb; mmX(acc, ug, &sm[SM_X], j, p0);
            #pragma unroll
            for (int i = 0; i < 4; i++) sm[SM_XU + 1 * 2048 + (p0 + i) * UNITS + j] = acc[i];
            bb = br[j];
            acc[0]=acc[1]=acc[2]=acc[3]=bb; mmX(acc, ur, &sm[SM_X], j, p0);
            #pragma unroll
            for (int i = 0; i < 4; i++) sm[SM_XU + 2 * 2048 + (p0 + i) * UNITS + j] = acc[i];
            bb = bh[j];
            acc[0]=acc[1]=acc[2]=acc[3]=bb; mmX(acc, uh, &sm[SM_X], j, p0);
            #pragma unroll
            for (int i = 0; i < 4; i++) sm[SM_XU + 3 * 2048 + (p0 + i) * UNITS + j] = acc[i];
            bb = b1[j];
            acc[0]=acc[1]=acc[2]=acc[3]=bb; mmX(acc, w1, &sm[SM_X], j, p0);
            #pragma unroll
            for (int p = 0; p < 4; p++) s_cur[p] = ftanh(acc[p]);
            st4(&sm[SM_S + 0 * 2048], s_cur, j, p0);
        }
        __syncthreads();

        // ---- forward ----
        #pragma unroll 1
        for (int l = 0; l < 3; l++) {
            float* Sin = &sm[SM_S + l * 2048];
            float* ZA  = &sm[SM_Z + l * 2048];
            float* GA  = &sm[SM_G + l * 2048];
            float* RA  = &sm[SM_R + l * 2048];
            float* HA  = &sm[SM_H + l * 2048];
            float* SR  = &sm[SM_SR];

            float z4[4], g4[4], h4[4];
            {
                u64t az0, az1, ag0, ag1, ar0, ar1;
                ldxu(az0, az1, &sm[SM_XU + 0 * 2048], j, p0);
                ldxu(ag0, ag1, &sm[SM_XU + 1 * 2048], j, p0);
                ldxu(ar0, ar1, &sm[SM_XU + 2 * 2048], j, p0);
                #pragma unroll 4
                for (int k = 0; k < UNITS; k++) {
                    float wzv = wz[k * UNITS + j];
                    float wgv = wg[k * UNITS + j];
                    float wrv = wr[k * UNITS + j];
                    u64t wzp = pack2(wzv, wzv);
                    u64t wgp = pack2(wgv, wgv);
                    u64t wrp = pack2(wrv, wrv);
                    ulonglong2 s = *(const ulonglong2*)&Sin[k * TP + p0];
                    az0 = ffma2(s.x, wzp, az0); az1 = ffma2(s.y, wzp, az1);
                    ag0 = ffma2(s.x, wgp, ag0); ag1 = ffma2(s.y, wgp, ag1);
                    ar0 = ffma2(s.x, wrp, ar0); ar1 = ffma2(s.y, wrp, ar1);
                }
                float r4[4], sr4[4];
                tanh4(z4, az0, az1);
                tanh4(g4, ag0, ag1);
                tanh4(r4, ar0, ar1);
                st4(ZA, z4, j, p0);
                st4(GA, g4, j, p0);
                st4(RA, r4, j, p0);
                #pragma unroll
                for (int p = 0; p < 4; p++) sr4[p] = s_cur[p] * r4[p];
                st4(SR, sr4, j, p0);
            }
            __syncthreads();
            {
                u64t ah0, ah1;
                ldxu(ah0, ah1, &sm[SM_XU + 3 * 2048], j, p0);
                mm1(ah0, ah1, wh, SR, j, p0);
                tanh4(h4, ah0, ah1);
                st4(HA, h4, j, p0);
            }
            #pragma unroll
            for (int p = 0; p < 4; p++)
                s_cur[p] = (1.0f - g4[p]) * h4[p] + z4[p] * s_cur[p];
            if (l < 2) st4(&sm[SM_S + (l + 1) * 2048], s_cur, j, p0);
            __syncthreads();
        }

        // ---- value f = s3@w + b ----
        {
            float wv = wout[j];
            int warpId = tid >> 5;
            #pragma unroll
            for (int p = 0; p < 4; p++) {
                float v = wv * s_cur[p];
                #pragma unroll
                for (int off = 16; off; off >>= 1) v += __shfl_xor_sync(0xffffffffu, v, off);
                if ((tid & 31) == 0) sm[SM_FRED + warpId * 4 + p] = v;
            }
            __syncthreads();
            if (tid < TP) {
                int p = tid;
                int pgp = p >> 2;
                float f = bout[0];
                #pragma unroll
                for (int q = 0; q < 4; q++) f += sm[SM_FRED + (pgp * 4 + q) * 4 + (p & 3)];
                g_FVAL[base + p] = f;
            }
        }

        if (!doGrad) continue;

        // ---- backward (no register Σda — per-layer da stays in Z/G/R/H slots) ----
        float ds[4];
        {
            float wv = wout[j];
            #pragma unroll
            for (int p = 0; p < 4; p++) ds[p] = wv;
        }

        #pragma unroll 1
        for (int l = 2; l >= 0; l--) {
            float* Sin = &sm[SM_S + l * 2048];
            float* ZA  = &sm[SM_Z + l * 2048];
            float* GA  = &sm[SM_G + l * 2048];
            float* RA  = &sm[SM_R + l * 2048];
            float* HA  = &sm[SM_H + l * 2048];

            // stage A
            {
                float z4[4], g4[4], h4[4], sl4[4];
                {
                    float4 t;
                    t = *(const float4*)&ZA[j * TP + p0];  z4[0]=t.x; z4[1]=t.y; z4[2]=t.z; z4[3]=t.w;
                    t = *(const float4*)&GA[j * TP + p0];  g4[0]=t.x; g4[1]=t.y; g4[2]=t.z; g4[3]=t.w;
                    t = *(const float4*)&HA[j * TP + p0];  h4[0]=t.x; h4[1]=t.y; h4[2]=t.z; h4[3]=t.w;
                    t = *(const float4*)&Sin[j * TP + p0]; sl4[0]=t.x; sl4[1]=t.y; sl4[2]=t.z; sl4[3]=t.w;
                }
                float daz[4], dag[4], dah[4];
                #pragma unroll
                for (int p = 0; p < 4; p++) {
                    float dsp = ds[p];
                    float dh = dsp * (1.0f - g4[p]);
                    float dg = -dsp * h4[p];
                    float dz = dsp * sl4[p];
                    daz[p] = dz * (1.0f - z4[p] * z4[p]);
                    dag[p] = dg * (1.0f - g4[p] * g4[p]);
                    dah[p] = dh * (1.0f - h4[p] * h4[p]);
                    ds[p] = dsp * z4[p];
                }
                st4(ZA, daz, j, p0);
                st4(GA, dag, j, p0);
                st4(HA, dah, j, p0);
            }
            __syncthreads();

            // stage B: dsr = dah @ Wh^T
            float dsr[4];
            {
                u64t b0 = pack2(0.f, 0.f), b1p = pack2(0.f, 0.f);
                mm1(b0, b1p, g_WT + 3 * UNITS * UNITS, HA, j, p0);
                float2 t0 = unpack2(b0), t1 = unpack2(b1p);
                dsr[0] = t0.x; dsr[1] = t0.y; dsr[2] = t1.x; dsr[3] = t1.y;
            }

            // stage C
            {
                float r4[4], sl4[4], dar[4];
                {
                    float4 t;
                    t = *(const float4*)&RA[j * TP + p0];  r4[0]=t.x; r4[1]=t.y; r4[2]=t.z; r4[3]=t.w;
                    t = *(const float4*)&Sin[j * TP + p0]; sl4[0]=t.x; sl4[1]=t.y; sl4[2]=t.z; sl4[3]=t.w;
                }
                #pragma unroll
                for (int p = 0; p < 4; p++) {
                    ds[p] += dsr[p] * r4[p];
                    dar[p] = (dsr[p] * sl4[p]) * (1.0f - r4[p] * r4[p]);
                }
                st4(RA, dar, j, p0);
            }
            __syncthreads();

            // stage D
            {
                const float* WzT = g_WT + 0 * UNITS * UNITS;
                const float* WgT = g_WT + 1 * UNITS * UNITS;
                const float* WrT = g_WT + 2 * UNITS * UNITS;
                u64t d0 = pack2(ds[0], ds[1]), d1 = pack2(ds[2], ds[3]);
                #pragma unroll 4
                for (int k = 0; k < UNITS; k++) {
                    float az = WzT[k * UNITS + j];
                    float ag = WgT[k * UNITS + j];
                    float ar = WrT[k * UNITS + j];
                    u64t azp = pack2(az, az);
                    u64t agp = pack2(ag, ag);
                    u64t arp = pack2(ar, ar);
                    ulonglong2 zz = *(const ulonglong2*)&ZA[k * TP + p0];
                    ulonglong2 gg = *(const ulonglong2*)&GA[k * TP + p0];
                    ulonglong2 rr = *(const ulonglong2*)&RA[k * TP + p0];
                    d0 = ffma2(zz.x, azp, d0); d1 = ffma2(zz.y, azp, d1);
                    d0 = ffma2(gg.x, agp, d0); d1 = ffma2(gg.y, agp, d1);
                    d0 = ffma2(rr.x, arp, d0); d1 = ffma2(rr.y, arp, d1);
                }
                float2 t0 = unpack2(d0), t1 = unpack2(d1);
                ds[0] = t0.x; ds[1] = t0.y; ds[2] = t1.x; ds[3] = t1.y;
            }
            // next stage A writes only layer l-1 slots at own row: no barrier needed
        }

        // all stage-D readers must finish before layer-0 slots are combined
        __syncthreads();
        {
            int o = j * TP + p0;
            float4 a, b2, c;
            // Σ_l da into layer-0 arrays
            a = *(const float4*)&sm[SM_Z + o]; b2 = *(const float4*)&sm[SM_Z + 2048 + o]; c = *(const float4*)&sm[SM_Z + 4096 + o];
            *(float4*)&sm[SM_Z + o] = make_float4(a.x+b2.x+c.x, a.y+b2.y+c.y, a.z+b2.z+c.z, a.w+b2.w+c.w);
            a = *(const float4*)&sm[SM_G + o]; b2 = *(const float4*)&sm[SM_G + 2048 + o]; c = *(const float4*)&sm[SM_G + 4096 + o];
            *(float4*)&sm[SM_G + o] = make_float4(a.x+b2.x+c.x, a.y+b2.y+c.y, a.z+b2.z+c.z, a.w+b2.w+c.w);
            a = *(const float4*)&sm[SM_R + o]; b2 = *(const float4*)&sm[SM_R + 2048 + o]; c = *(const float4*)&sm[SM_R + 4096 + o];
            *(float4*)&sm[SM_R + o] = make_float4(a.x+b2.x+c.x, a.y+b2.y+c.y, a.z+b2.z+c.z, a.w+b2.w+c.w);
            a = *(const float4*)&sm[SM_H + o]; b2 = *(const float4*)&sm[SM_H + 2048 + o]; c = *(const float4*)&sm[SM_H + 4096 + o];
            *(float4*)&sm[SM_H + o] = make_float4(a.x+b2.x+c.x, a.y+b2.y+c.y, a.z+b2.z+c.z, a.w+b2.w+c.w);
            // da1 -> SR
            float4 sq = *(const float4*)&sm[SM_S + o];
            float s0s[4] = {sq.x, sq.y, sq.z, sq.w};
            float da1[4];
            #pragma unroll
            for (int p = 0; p < 4; p++) da1[p] = ds[p] * (1.0f - s0s[p] * s0s[p]);
            *(float4*)&sm[SM_SR + o] = make_float4(da1[0], da1[1], da1[2], da1[3]);
        }
        __syncthreads();

        // dx = Σ_v Da_v @ U_v^T
        if (tid < DD * TP) {
            int d = tid % DD;
            int p = tid / DD;
            float acc = 0.f;
            #pragma unroll 1
            for (int v = 0; v < 5; v++) {
                const float* slot =
                    (v == 0) ? &sm[SM_Z] : (v == 1) ? &sm[SM_G] :
                    (v == 2) ? &sm[SM_R] : (v == 3) ? &sm[SM_H] : &sm[SM_SR];
                const float* Ut = g_UcatT + v * UNITS * 24;
                #pragma unroll 8
                for (int k = 0; k < UNITS; k++)
                    acc += slot[k * TP + p] * Ut[k * 24 + d];
            }
            g_FP[base * DD + tid] = acc;
        }
    }

    grid_barrier();

    // ================= phase 2: epilogue =================
    {
        int warpId = tid >> 5;
        int lane   = tid & 31;
        int n = cta * 16 + warpId;
        if (n < NPT) {
            const float* fp1 = &g_FP[n * DD];
            const float* x1r = &g_X[n * DD];
            int rp = (4096 + lane * NPT + n) * DD;
            const float* fpp = &g_FP[rp];
            const float* xp  = &g_X[rp];

            float part = 0.f;
            #pragma unroll
            for (int k = 0; k < DIMX; k++) {
                float viol = xp[k] - x1r[k];
                part += (fpp[k] - fp1[k]) * viol;
            }
            #pragma unroll
            for (int off = 16; off; off >>= 1) part += __shfl_xor_sync(0xffffffffu, part, off);

            if (lane == 0) {
                float term12 = part / (DELTAc * (float)MCc);
                float term11 = fp1[DIMX];
                #pragma unroll
                for (int k = 0; k < DIMX; k++) term11 += MUc * x1r[k] * fp1[k];
                out[n] = term11 + 0.5f * term12 - Rc * g_FVAL[n];

                const float* x2r = &g_X[(NPT + n) * DD];
                float prod = 1.f;
                #pragma unroll
                for (int k = 0; k < DIMX; k++) prod *= x2r[k];
                float payoff = powf(prod, 1.0f / (float)DIMX);
                payoff = fmaxf(payoff, 0.f);
                out[NPT + n] = g_FVAL[NPT + n] - payoff;
            }
        }
    }
}

extern "C" void kernel_launch(void* const* d_in, const int* in_sizes, int n_in,
                              void* d_out, int out_size)
{
    (void)in_sizes; (void)n_in; (void)out_size;
    const float* inputs = (const float*)d_in[0];
    const float* eps    = (const float*)d_in[1];
    const float* w1  = (const float*)d_in[2];
    const float* b1  = (const float*)d_in[3];
    const float* uzl = (const float*)d_in[4];
    const float* wzl = (const float*)d_in[5];
    const float* bzl = (const float*)d_in[6];
    const float* ugl = (const float*)d_in[7];
    const float* wgl = (const float*)d_in[8];
    const float* bgl = (const float*)d_in[9];
    const float* url = (const float*)d_in[10];
    const float* wrl = (const float*)d_in[11];
    const float* brl = (const float*)d_in[12];
    const float* uhl = (const float*)d_in[13];
    const float* whl = (const float*)d_in[14];
    const float* bhl = (const float*)d_in[15];
    const float* w   = (const float*)d_in[16];
    const float* b   = (const float*)d_in[17];
    float* out = (float*)d_out;

    const int smem_bytes = SM_TOT * (int)sizeof(float);
    cudaFuncSetAttribute(dgm_persistent, cudaFuncAttributeMaxDynamicSharedMemorySize, smem_bytes);

    dgm_persistent<<<NCTA, THREADS, smem_bytes>>>(
        inputs, eps, w1, b1, uzl, wzl, bzl, ugl, wgl, bgl,
        url, wrl, brl, uhl, whl, bhl, w, b, out);
}

// round 17
// speedup vs baseline: 1.0742x; 1.0742x over previous
#include <cuda_runtime.h>
#include <stdint.h>
#include <math.h>

#define DIMX   20
#define DD     21
#define NPT    2048
#define MCc    32
#define UNITS  128
#define TP     16
#define BTOT   69632
#define NTILES (BTOT / TP)
#define THREADS 512
#define NCTA   148

#define SIGc   0.2f
#define MUc    0.05f
#define Rc     0.05f
#define DELTAc 0.01f

#define MAT_FLOATS (UNITS * UNITS)      // 16384
#define CHUNK_FLOATS 8192               // half a matrix = 32 KB
#define NCHUNK_FULL 48                  // 24 passes * 2
#define NCHUNK_FWD  24                  // forward-only tiles

__device__ float g_Warena[8 * MAT_FLOATS];  // 0..3: wz,wg,wr,wh ; 4..7: WzT,WgT,WrT,WhT
__device__ float g_UcatT[5 * UNITS * 24];
__device__ float g_X[BTOT * DD];
__device__ float g_FP[BTOT * DD];
__device__ float g_FVAL[BTOT];
__device__ unsigned g_bar = 0;

// smem layout (floats)
#define SM_WB   0                        // 2 x 8192 weight chunks
#define SM_X    (SM_WB + 2 * CHUNK_FLOATS)   // 336
#define SM_S    (SM_X + 336)             // 3 x 2048
#define SM_Z    (SM_S + 3 * 2048)
#define SM_G    (SM_Z + 3 * 2048)
#define SM_R    (SM_G + 3 * 2048)
#define SM_H    (SM_R + 3 * 2048)
#define SM_SR   (SM_H + 3 * 2048)        // 2048
#define SM_FRED (SM_SR + 2048)           // 64
#define SM_TOT  (SM_FRED + 64)           // 49552 floats = 198208 B

typedef unsigned long long u64t;

__device__ __forceinline__ u64t pack2(float lo, float hi) {
    u64t r;
    asm("mov.b64 %0, {%1, %2};" : "=l"(r) : "f"(lo), "f"(hi));
    return r;
}
__device__ __forceinline__ float2 unpack2(u64t v) {
    float2 f;
    asm("mov.b64 {%0, %1}, %2;" : "=f"(f.x), "=f"(f.y) : "l"(v));
    return f;
}
__device__ __forceinline__ u64t ffma2(u64t a, u64t b, u64t c) {
    u64t d;
    asm("fma.rn.f32x2 %0, %1, %2, %3;" : "=l"(d) : "l"(a), "l"(b), "l"(c));
    return d;
}
__device__ __forceinline__ float ftanh(float x) {
    float ax = fabsf(x);
    float t = __expf(-2.0f * ax);
    float r = __fdividef(1.0f - t, 1.0f + t);
    return copysignf(r, x);
}
__device__ __forceinline__ void tanh4(float out[4], u64t a0, u64t a1) {
    float2 t0 = unpack2(a0), t1 = unpack2(a1);
    out[0] = ftanh(t0.x); out[1] = ftanh(t0.y); out[2] = ftanh(t1.x); out[3] = ftanh(t1.y);
}
__device__ __forceinline__ void st4(float* dst, const float a[4], int j, int p0) {
    *(float4*)&dst[j * TP + p0] = make_float4(a[0], a[1], a[2], a[3]);
}
__device__ __forceinline__ void mmX(float acc[4], const float* __restrict__ U,
                                    const float* X, int j, int p0) {
    #pragma unroll
    for (int d = 0; d < DD; d++) {
        float wv = U[d * UNITS + j];
        float4 s = *(const float4*)&X[d * TP + p0];
        acc[0] += s.x * wv; acc[1] += s.y * wv; acc[2] += s.z * wv; acc[3] += s.w * wv;
    }
}

// ---- cp.async machinery ----
template<int N> __device__ __forceinline__ void cp_wait() {
    asm volatile("cp.async.wait_group %0;" :: "n"(N) : "memory");
}
__device__ __forceinline__ void stage_chunk(float* dst, const float* src, int tid) {
    uint32_t sa = (uint32_t)__cvta_generic_to_shared(dst);
    #pragma unroll
    for (int i = 0; i < 4; i++) {
        int idx = tid + i * THREADS;       // float4 index < 2048
        asm volatile("cp.async.cg.shared.global [%0], [%1], 16;"
                     :: "r"(sa + (uint32_t)idx * 16u), "l"(src + idx * 4) : "memory");
    }
    asm volatile("cp.async.commit_group;" ::: "memory");
}
// chunk c -> source pointer. pass p=c/2: p<12 -> wz,wg,wr,wh cyclic; p>=12 -> WhT,WzT,WgT,WrT cyclic
__device__ __forceinline__ const float* chunk_src(int c) {
    int p = c >> 1;
    int mat;
    if (p < 12) mat = p & 3;
    else { int q = p & 3; mat = (q == 0) ? 7 : 3 + q; }
    return g_Warena + mat * MAT_FLOATS + (c & 1) * CHUNK_FLOATS;
}
__device__ __forceinline__ void chunk_pre(int cc, int lim) {
    if (cc == lim - 1) cp_wait<0>(); else cp_wait<1>();
    __syncthreads();
}
__device__ __forceinline__ void chunk_post(int& cc, int lim, float* smw, int tid) {
    __syncthreads();
    if (cc + 2 < lim) stage_chunk(smw + ((cc + 2) & 1) * CHUNK_FLOATS, chunk_src(cc + 2), tid);
    cc++;
}
// one matmul pass (2 chunks): acc += Sop^T-pairs * W_staged
__device__ __forceinline__ void pass2(u64t& a0, u64t& a1, const float* Sop,
                                      float* smw, int& cc, int lim,
                                      int tid, int j, int p0) {
    #pragma unroll 1
    for (int h2 = 0; h2 < 2; h2++) {
        chunk_pre(cc, lim);
        const float* W = smw + ((cc & 1) ? CHUNK_FLOATS : 0);
        const float* Sb = Sop + h2 * 64 * TP;
        #pragma unroll 8
        for (int kk = 0; kk < 64; kk++) {
            float wv = W[kk * UNITS + j];
            u64t wp = pack2(wv, wv);
            ulonglong2 s = *(const ulonglong2*)&Sb[kk * TP + p0];
            a0 = ffma2(s.x, wp, a0);
            a1 = ffma2(s.y, wp, a1);
        }
        chunk_post(cc, lim, smw, tid);
    }
}

// grid barrier: monotonic counter, safe across graph replays
__device__ __forceinline__ void grid_barrier() {
    __syncthreads();
    if (threadIdx.x == 0) {
        __threadfence();
        unsigned old = atomicAdd(&g_bar, 1u);
        unsigned target = (old / NCTA + 1u) * NCTA;
        while (*(volatile unsigned*)&g_bar < target) { }
        __threadfence();
    }
    __syncthreads();
}

__global__ __launch_bounds__(THREADS, 1)
void dgm_persistent(const float* __restrict__ inputs, const float* __restrict__ eps,
                    const float* __restrict__ w1, const float* __restrict__ b1,
                    const float* __restrict__ uz, const float* __restrict__ wz, const float* __restrict__ bz,
                    const float* __restrict__ ug, const float* __restrict__ wg, const float* __restrict__ bg,
                    const float* __restrict__ ur, const float* __restrict__ wr, const float* __restrict__ br,
                    const float* __restrict__ uh, const float* __restrict__ wh, const float* __restrict__ bh,
                    const float* __restrict__ wout, const float* __restrict__ bout,
                    float* __restrict__ out)
{
    extern __shared__ float sm[];
    float* smw = &sm[SM_WB];
    const int tid = threadIdx.x;
    const int cta = blockIdx.x;
    const int gthread = cta * THREADS + tid;
    const int gstride = NCTA * THREADS;

    // ================= phase 0: weight arena + UcatT + X build =================
    for (int t = gthread; t < 8 * MAT_FLOATS; t += gstride) {
        int mat = t >> 14;
        int r   = t & 16383;
        float v;
        if (mat < 4) {
            const float* W = (mat == 0) ? wz : (mat == 1) ? wg : (mat == 2) ? wr : wh;
            v = W[r];
        } else {
            int a = r >> 7, b2 = r & 127;
            const float* W = (mat == 4) ? wz : (mat == 5) ? wg : (mat == 6) ? wr : wh;
            v = W[b2 * UNITS + a];
        }
        g_Warena[t] = v;
    }
    for (int t = gthread; t < 5 * UNITS * 24; t += gstride) {
        int v = t / (UNITS * 24);
        int r = t % (UNITS * 24);
        int jj = r / 24;
        int d = r % 24;
        const float* U = (v == 0) ? uz : (v == 1) ? ug : (v == 2) ? ur : (v == 3) ? uh : w1;
        g_UcatT[t] = (d < DD) ? U[d * UNITS + jj] : 0.0f;
    }

    if (tid == 0) {
        double Ld[DIMX][DIMX];
        for (int i = 0; i < DIMX; i++) {
            for (int j2 = 0; j2 <= i; j2++) {
                double s = 0.01 * (0.5 + (i == j2 ? 0.5 : 0.0));
                for (int k = 0; k < j2; k++) s -= Ld[i][k] * Ld[j2][k];
                Ld[i][j2] = (i == j2) ? sqrt(s) : s / Ld[j2][j2];
            }
        }
        for (int i = 0; i < DIMX; i++)
            for (int j2 = 0; j2 < DIMX; j2++)
                sm[SM_SR + i * DIMX + j2] = (j2 <= i) ? (float)Ld[i][j2] : 0.0f;
    }
    __syncthreads();
    const float* Lsm = &sm[SM_SR];

    for (int r = gthread; r < BTOT; r += gstride) {
        if (r < 4096) {
            #pragma unroll
            for (int d = 0; d < DD; d++) g_X[r * DD + d] = inputs[r * DD + d];
        } else {
            int q = r - 4096;
            int m = q >> 11;
            int n = q & 2047;
            float xr[DD];
            #pragma unroll
            for (int d = 0; d < DD; d++) xr[d] = inputs[n * DD + d];
            float e[DIMX];
            #pragma unroll
            for (int d = 0; d < DIMX; d++) e[d] = eps[(m * NPT + n) * DIMX + d];
            #pragma unroll
            for (int k = 0; k < DIMX; k++) {
                float acc = 0.f;
                #pragma unroll
                for (int d = 0; d < DIMX; d++) acc += e[d] * Lsm[k * DIMX + d];
                float sample = xr[k] + acc;
                float viol = sample * (SIGc * xr[k]);
                g_X[r * DD + k] = xr[k] + viol;
            }
            g_X[r * DD + DIMX] = xr[DIMX];
        }
    }

    grid_barrier();

    // ================= phase 1: tile loop =================
    const int j  = tid & 127;
    const int pg = tid >> 7;
    const int p0 = pg * 4;

    for (int tile = cta; tile < NTILES; tile += NCTA) {
        const int base = tile * TP;
        const bool doGrad = !(tile >= 128 && tile < 256);
        const int lim = doGrad ? NCHUNK_FULL : NCHUNK_FWD;
        int cc = 0;

        __syncthreads();   // prior tile fully done with smw + activation smem
        stage_chunk(smw + 0, chunk_src(0), tid);
        stage_chunk(smw + CHUNK_FLOATS, chunk_src(1), tid);

        for (int t = tid; t < TP * DD; t += THREADS) {
            int p = t / DD, d = t % DD;
            sm[SM_X + d * TP + p] = g_X[(base + p) * DD + d];
        }
        __syncthreads();

        // ---- prologue: x@U + b, kept as f32x2 register pairs ----
        u64t xzr[2], xgr[2], xrr[2], xhr[2];
        float s_cur[4];
        {
            float acc[4];
            float bb;
            bb = bz[j];
            acc[0]=acc[1]=acc[2]=acc[3]=bb; mmX(acc, uz, &sm[SM_X], j, p0);
            xzr[0] = pack2(acc[0], acc[1]); xzr[1] = pack2(acc[2], acc[3]);
            bb = bg[j];
            acc[0]=acc[1]=acc[2]=acc[3]=bb; mmX(acc, ug, &sm[SM_X], j, p0);
            xgr[0] = pack2(acc[0], acc[1]); xgr[1] = pack2(acc[2], acc[3]);
            bb = br[j];
            acc[0]=acc[1]=acc[2]=acc[3]=bb; mmX(acc, ur, &sm[SM_X], j, p0);
            xrr[0] = pack2(acc[0], acc[1]); xrr[1] = pack2(acc[2], acc[3]);
            bb = bh[j];
            acc[0]=acc[1]=acc[2]=acc[3]=bb; mmX(acc, uh, &sm[SM_X], j, p0);
            xhr[0] = pack2(acc[0], acc[1]); xhr[1] = pack2(acc[2], acc[3]);
            bb = b1[j];
            acc[0]=acc[1]=acc[2]=acc[3]=bb; mmX(acc, w1, &sm[SM_X], j, p0);
            #pragma unroll
            for (int p = 0; p < 4; p++) s_cur[p] = ftanh(acc[p]);
            st4(&sm[SM_S + 0 * 2048], s_cur, j, p0);
        }
        // no extra barrier: first chunk_pre syncs before any staged-weight read,
        // and S0 is only read after that sync.

        // ---- forward: 4 passes per layer (wz, wg, wr, wh) ----
        #pragma unroll 1
        for (int l = 0; l < 3; l++) {
            float* Sin = &sm[SM_S + l * 2048];
            float* ZA  = &sm[SM_Z + l * 2048];
            float* GA  = &sm[SM_G + l * 2048];
            float* RA  = &sm[SM_R + l * 2048];
            float* HA  = &sm[SM_H + l * 2048];
            float* SR  = &sm[SM_SR];

            float z4[4], g4[4], h4[4];
            u64t a0, a1;

            a0 = xzr[0]; a1 = xzr[1];
            pass2(a0, a1, Sin, smw, cc, lim, tid, j, p0);
            tanh4(z4, a0, a1);
            st4(ZA, z4, j, p0);

            a0 = xgr[0]; a1 = xgr[1];
            pass2(a0, a1, Sin, smw, cc, lim, tid, j, p0);
            tanh4(g4, a0, a1);
            st4(GA, g4, j, p0);

            a0 = xrr[0]; a1 = xrr[1];
            pass2(a0, a1, Sin, smw, cc, lim, tid, j, p0);
            {
                float r4[4], sr4[4];
                tanh4(r4, a0, a1);
                st4(RA, r4, j, p0);
                #pragma unroll
                for (int p = 0; p < 4; p++) sr4[p] = s_cur[p] * r4[p];
                st4(SR, sr4, j, p0);
            }

            a0 = xhr[0]; a1 = xhr[1];
            pass2(a0, a1, SR, smw, cc, lim, tid, j, p0);
            tanh4(h4, a0, a1);
            st4(HA, h4, j, p0);

            #pragma unroll
            for (int p = 0; p < 4; p++)
                s_cur[p] = (1.0f - g4[p]) * h4[p] + z4[p] * s_cur[p];
            if (l < 2) st4(&sm[SM_S + (l + 1) * 2048], s_cur, j, p0);
        }

        // ---- value f = s3@w + b ----
        __syncthreads();
        {
            float wv = wout[j];
            int warpId = tid >> 5;
            #pragma unroll
            for (int p = 0; p < 4; p++) {
                float v = wv * s_cur[p];
                #pragma unroll
                for (int off = 16; off; off >>= 1) v += __shfl_xor_sync(0xffffffffu, v, off);
                if ((tid & 31) == 0) sm[SM_FRED + warpId * 4 + p] = v;
            }
            __syncthreads();
            if (tid < TP) {
                int p = tid;
                int pgp = p >> 2;
                float f = bout[0];
                #pragma unroll
                for (int q = 0; q < 4; q++) f += sm[SM_FRED + (pgp * 4 + q) * 4 + (p & 3)];
                g_FVAL[base + p] = f;
            }
        }

        if (!doGrad) continue;

        // ---- backward: per layer A, BB(WhT), C, BD(WzT,WgT,WrT) ----
        float ds[4];
        {
            float wv = wout[j];
            #pragma unroll
            for (int p = 0; p < 4; p++) ds[p] = wv;
        }

        #pragma unroll 1
        for (int l = 2; l >= 0; l--) {
            float* Sin = &sm[SM_S + l * 2048];
            float* ZA  = &sm[SM_Z + l * 2048];
            float* GA  = &sm[SM_G + l * 2048];
            float* RA  = &sm[SM_R + l * 2048];
            float* HA  = &sm[SM_H + l * 2048];

            // stage A: own cells only; overwrite Z/G/H with daz/dag/dah
            {
                float z4[4], g4[4], h4[4], sl4[4];
                {
                    float4 t;
                    t = *(const float4*)&ZA[j * TP + p0];  z4[0]=t.x; z4[1]=t.y; z4[2]=t.z; z4[3]=t.w;
                    t = *(const float4*)&GA[j * TP + p0];  g4[0]=t.x; g4[1]=t.y; g4[2]=t.z; g4[3]=t.w;
                    t = *(const float4*)&HA[j * TP + p0];  h4[0]=t.x; h4[1]=t.y; h4[2]=t.z; h4[3]=t.w;
                    t = *(const float4*)&Sin[j * TP + p0]; sl4[0]=t.x; sl4[1]=t.y; sl4[2]=t.z; sl4[3]=t.w;
                }
                float daz[4], dag[4], dah[4];
                #pragma unroll
                for (int p = 0; p < 4; p++) {
                    float dsp = ds[p];
                    float dh = dsp * (1.0f - g4[p]);
                    float dg = -dsp * h4[p];
                    float dz = dsp * sl4[p];
                    daz[p] = dz * (1.0f - z4[p] * z4[p]);
                    dag[p] = dg * (1.0f - g4[p] * g4[p]);
                    dah[p] = dh * (1.0f - h4[p] * h4[p]);
                    ds[p] = dsp * z4[p];
                }
                st4(ZA, daz, j, p0);
                st4(GA, dag, j, p0);
                st4(HA, dah, j, p0);
            }
            // BB: dsr = dah @ WhT  (chunk_pre's sync orders the HA writes)
            float dsr[4];
            {
                u64t b0 = pack2(0.f, 0.f), b1p = pack2(0.f, 0.f);
                pass2(b0, b1p, HA, smw, cc, lim, tid, j, p0);
                float2 t0 = unpack2(b0), t1 = unpack2(b1p);
                dsr[0] = t0.x; dsr[1] = t0.y; dsr[2] = t1.x; dsr[3] = t1.y;
            }
            // stage C: own cells; overwrite R with dar
            {
                float r4[4], sl4[4], dar[4];
                {
                    float4 t;
                    t = *(const float4*)&RA[j * TP + p0];  r4[0]=t.x; r4[1]=t.y; r4[2]=t.z; r4[3]=t.w;
                    t = *(const float4*)&Sin[j * TP + p0]; sl4[0]=t.x; sl4[1]=t.y; sl4[2]=t.z; sl4[3]=t.w;
                }
                #pragma unroll
                for (int p = 0; p < 4; p++) {
                    ds[p] += dsr[p] * r4[p];
                    dar[p] = (dsr[p] * sl4[p]) * (1.0f - r4[p] * r4[p]);
                }
                st4(RA, dar, j, p0);
            }
            // BD: ds += daz@WzT + dag@WgT + dar@WrT
            {
                u64t d0 = pack2(ds[0], ds[1]), d1 = pack2(ds[2], ds[3]);
                pass2(d0, d1, ZA, smw, cc, lim, tid, j, p0);
                pass2(d0, d1, GA, smw, cc, lim, tid, j, p0);
                pass2(d0, d1, RA, smw, cc, lim, tid, j, p0);
                float2 t0 = unpack2(d0), t1 = unpack2(d1);
                ds[0] = t0.x; ds[1] = t0.y; ds[2] = t1.x; ds[3] = t1.y;
            }
        }

        // combine Σ_l da into layer-0 slots (own cells; readers done at last chunk sync)
        {
            int o = j * TP + p0;
            float4 a, b2, c;
            a = *(const float4*)&sm[SM_Z + o]; b2 = *(const float4*)&sm[SM_Z + 2048 + o]; c = *(const float4*)&sm[SM_Z + 4096 + o];
            *(float4*)&sm[SM_Z + o] = make_float4(a.x+b2.x+c.x, a.y+b2.y+c.y, a.z+b2.z+c.z, a.w+b2.w+c.w);
            a = *(const float4*)&sm[SM_G + o]; b2 = *(const float4*)&sm[SM_G + 2048 + o]; c = *(const float4*)&sm[SM_G + 4096 + o];
            *(float4*)&sm[SM_G + o] = make_float4(a.x+b2.x+c.x, a.y+b2.y+c.y, a.z+b2.z+c.z, a.w+b2.w+c.w);
            a = *(const float4*)&sm[SM_R + o]; b2 = *(const float4*)&sm[SM_R + 2048 + o]; c = *(const float4*)&sm[SM_R + 4096 + o];
            *(float4*)&sm[SM_R + o] = make_float4(a.x+b2.x+c.x, a.y+b2.y+c.y, a.z+b2.z+c.z, a.w+b2.w+c.w);
            a = *(const float4*)&sm[SM_H + o]; b2 = *(const float4*)&sm[SM_H + 2048 + o]; c = *(const float4*)&sm[SM_H + 4096 + o];
            *(float4*)&sm[SM_H + o] = make_float4(a.x+b2.x+c.x, a.y+b2.y+c.y, a.z+b2.z+c.z, a.w+b2.w+c.w);
            float4 sq = *(const float4*)&sm[SM_S + o];
            float da1[4];
            #pragma unroll
            for (int p = 0; p < 4; p++) {
                float s0 = (p == 0) ? sq.x : (p == 1) ? sq.y : (p == 2) ? sq.z : sq.w;
                da1[p] = ds[p] * (1.0f - s0 * s0);
            }
            *(float4*)&sm[SM_SR + o] = make_float4(da1[0], da1[1], da1[2], da1[3]);
        }
        __syncthreads();

        // dx = Σ_v Da_v @ U_v^T
        if (tid < DD * TP) {
            int d = tid % DD;
            int p = tid / DD;
            float acc = 0.f;
            #pragma unroll 1
            for (int v = 0; v < 5; v++) {
                const float* slot =
                    (v == 0) ? &sm[SM_Z] : (v == 1) ? &sm[SM_G] :
                    (v == 2) ? &sm[SM_R] : (v == 3) ? &sm[SM_H] : &sm[SM_SR];
                const float* Ut = g_UcatT + v * UNITS * 24;
                #pragma unroll 8
                for (int k = 0; k < UNITS; k++)
                    acc += slot[k * TP + p] * Ut[k * 24 + d];
            }
            g_FP[base * DD + tid] = acc;
        }
    }

    grid_barrier();

    // ================= phase 2: epilogue =================
    {
        int warpId = tid >> 5;
        int lane   = tid & 31;
        int n = cta * 16 + warpId;
        if (n < NPT) {
            const float* fp1 = &g_FP[n * DD];
            const float* x1r = &g_X[n * DD];
            int rp = (4096 + lane * NPT + n) * DD;
            const float* fpp = &g_FP[rp];
            const float* xp  = &g_X[rp];

            float part = 0.f;
            #pragma unroll
            for (int k = 0; k < DIMX; k++) {
                float viol = xp[k] - x1r[k];
                part += (fpp[k] - fp1[k]) * viol;
            }
            #pragma unroll
            for (int off = 16; off; off >>= 1) part += __shfl_xor_sync(0xffffffffu, part, off);

            if (lane == 0) {
                float term12 = part / (DELTAc * (float)MCc);
                float term11 = fp1[DIMX];
                #pragma unroll
                for (int k = 0; k < DIMX; k++) term11 += MUc * x1r[k] * fp1[k];
                out[n] = term11 + 0.5f * term12 - Rc * g_FVAL[n];

                const float* x2r = &g_X[(NPT + n) * DD];
                float prod = 1.f;
                #pragma unroll
                for (int k = 0; k < DIMX; k++) prod *= x2r[k];
                float payoff = powf(prod, 1.0f / (float)DIMX);
                payoff = fmaxf(payoff, 0.f);
                out[NPT + n] = g_FVAL[NPT + n] - payoff;
            }
        }
    }
}

extern "C" void kernel_launch(void* const* d_in, const int* in_sizes, int n_in,
                              void* d_out, int out_size)
{
    (void)in_sizes; (void)n_in; (void)out_size;
    const float* inputs = (const float*)d_in[0];
    const float* eps    = (const float*)d_in[1];
    const float* w1  = (const float*)d_in[2];
    const float* b1  = (const float*)d_in[3];
    const float* uzl = (const float*)d_in[4];
    const float* wzl = (const float*)d_in[5];
    const float* bzl = (const float*)d_in[6];
    const float* ugl = (const float*)d_in[7];
    const float* wgl = (const float*)d_in[8];
    const float* bgl = (const float*)d_in[9];
    const float* url = (const float*)d_in[10];
    const float* wrl = (const float*)d_in[11];
    const float* brl = (const float*)d_in[12];
    const float* uhl = (const float*)d_in[13];
    const float* whl = (const float*)d_in[14];
    const float* bhl = (const float*)d_in[15];
    const float* w   = (const float*)d_in[16];
    const float* b   = (const float*)d_in[17];
    float* out = (float*)d_out;

    const int smem_bytes = SM_TOT * (int)sizeof(float);
    cudaFuncSetAttribute(dgm_persistent, cudaFuncAttributeMaxDynamicSharedMemorySize, smem_bytes);

    dgm_persistent<<<NCTA, THREADS, smem_bytes>>>(
        inputs, eps, w1, b1, uzl, wzl, bzl, ugl, wgl, bgl,
        url, wrl, brl, uhl, whl, bhl, w, b, out);
}